// round 12
// baseline (speedup 1.0000x reference)
#include <cuda_runtime.h>
#include <cuda_fp16.h>
#include <cstdint>

#define NODES_MAX 100000
#define NPER 12
#define ROWH 16   // padded fp16 row: 16 halves = 32 B = one L2 sector

__device__ int    g_deg[NODES_MAX];          // zero-init at load; k_final re-zeroes each call
__device__ float  g_dinv[NODES_MAX];
__device__ __align__(32) __half g_yraw[NODES_MAX * ROWH];  // x as fp16, unscaled (written by k_deg)
__device__ __align__(32) __half g_yh[NODES_MAX * ROWH];    // y = x * dinv_src, fp16 (last 4 halves zero)
__device__ __align__(32) __half g_acch[NODES_MAX * ROWH];  // fp16 accumulator (seeded with y = self loop)
// folded coefficients: azh[4] (=az/2), bzh[4] (=bz/2), ah[4], bh[4], wh[12] (=softmax/2)
__device__ float g_cf[32];

// ---------------- K1: degree count (8 edges/thread) + x->fp16 convert + coef fold ----------------
__global__ void k_deg(const int* __restrict__ dst, int E,
                      const float* __restrict__ x, int n_nodes,
                      const float* __restrict__ cz_w, const float* __restrict__ cz_b,
                      const float* __restrict__ lz_w, const float* __restrict__ lz_b,
                      const float* __restrict__ ch_w, const float* __restrict__ ch_b,
                      const float* __restrict__ lh_w, const float* __restrict__ lh_b,
                      const float* __restrict__ att) {
    int i = blockIdx.x * blockDim.x + threadIdx.x;
    int e8 = E >> 3;
    if (i < e8) {
        int4 a = ((const int4*)dst)[2 * i];
        int4 b = ((const int4*)dst)[2 * i + 1];
        atomicAdd(&g_deg[a.x], 1);
        atomicAdd(&g_deg[a.y], 1);
        atomicAdd(&g_deg[a.z], 1);
        atomicAdd(&g_deg[a.w], 1);
        atomicAdd(&g_deg[b.x], 1);
        atomicAdd(&g_deg[b.y], 1);
        atomicAdd(&g_deg[b.z], 1);
        atomicAdd(&g_deg[b.w], 1);
    } else if (i == e8) {
        for (int r = e8 * 8; r < E; r++) atomicAdd(&g_deg[dst[r]], 1);
    }
    // overlap: convert x rows to raw fp16 using idle DRAM bandwidth
    if (i < n_nodes) {
        const float4* xr = (const float4*)(x + (size_t)i * NPER);
        float4 a = xr[0], b = xr[1], c = xr[2];
        __half2 h0 = __floats2half2_rn(a.x, a.y);
        __half2 h1 = __floats2half2_rn(a.z, a.w);
        __half2 h2 = __floats2half2_rn(b.x, b.y);
        __half2 h3 = __floats2half2_rn(b.z, b.w);
        __half2 h4 = __floats2half2_rn(c.x, c.y);
        __half2 h5 = __floats2half2_rn(c.z, c.w);
        uint4 lo, hi;
        lo.x = *(unsigned*)&h0; lo.y = *(unsigned*)&h1;
        lo.z = *(unsigned*)&h2; lo.w = *(unsigned*)&h3;
        hi.x = *(unsigned*)&h4; hi.y = *(unsigned*)&h5;
        hi.z = 0; hi.w = 0;
        uint4* row = (uint4*)(g_yraw + (size_t)i * ROWH);
        row[0] = lo;
        row[1] = hi;
    }
    if (blockIdx.x == 0 && threadIdx.x == 0) {
        for (int c = 0; c < 4; c++) {
            float a = 0.f, b = lz_b[c];
            float a2 = 0.f, b2 = lh_b[c];
            for (int k = 0; k < 4; k++) {
                float lz = lz_w[k * 4 + c];
                float lh = lh_w[k * 4 + c];
                a  += cz_w[k] * lz;
                b  += cz_b[k] * lz;
                a2 += ch_w[k] * lh;
                b2 += ch_b[k] * lh;
            }
            g_cf[c]     = 0.5f * a;   // halved: sigmoid(x) = 0.5 + 0.5*tanh(x/2)
            g_cf[4 + c] = 0.5f * b;
            g_cf[8 + c]  = a2;
            g_cf[12 + c] = b2;
        }
        float m = -1e30f;
        for (int p = 0; p < NPER; p++) m = fmaxf(m, att[p]);
        float sum = 0.f;
        float e[NPER];
        for (int p = 0; p < NPER; p++) { e[p] = __expf(att[p] - m); sum += e[p]; }
        float inv = 0.5f / sum;  // absorbs the 0.5 from (1-z) = 0.5*(1-t1)
        for (int p = 0; p < NPER; p++) g_cf[16 + p] = e[p] * inv;
    }
}

// ---------------- K2: dinv + scale raw fp16 rows; acc seeded with y (self loop) ----------------
__device__ __forceinline__ unsigned scaleh2(unsigned a, float s) {
    float2 f = __half22float2(*(__half2*)&a);
    __half2 r = __floats2half2_rn(f.x * s, f.y * s);
    return *(unsigned*)&r;
}

__global__ void k_prep(int n) {
    int i = blockIdx.x * blockDim.x + threadIdx.x;
    if (i >= n) return;
    float dinv = rsqrtf((float)(g_deg[i] + 1));  // +1 for self loop
    g_dinv[i] = dinv;
    const uint4* rr = (const uint4*)(g_yraw + (size_t)i * ROWH);
    uint4 r0 = rr[0];
    uint4 r1 = rr[1];
    uint4 lo, hi;
    lo.x = scaleh2(r0.x, dinv);
    lo.y = scaleh2(r0.y, dinv);
    lo.z = scaleh2(r0.z, dinv);
    lo.w = scaleh2(r0.w, dinv);
    hi.x = scaleh2(r1.x, dinv);
    hi.y = scaleh2(r1.y, dinv);
    hi.z = 0;
    hi.w = 0;
    uint4* row = (uint4*)(g_yh + (size_t)i * ROWH);
    row[0] = lo;
    row[1] = hi;
    // seed accumulator with the self-loop message:
    // final s = dinv * (y_self + sum_edges y_src) = dinv^2*x + dinv*sum
    uint4* arow = (uint4*)(g_acch + (size_t)i * ROWH);
    arow[0] = lo;
    arow[1] = hi;
}

// ---------------- K3: edge scatter, 2 lanes per edge (half-row tasks), 2 tasks/thread ----------------
__global__ void k_scatter(const int* __restrict__ src, const int* __restrict__ dst, int E) {
    int T = 2 * E;
    int stride = blockDim.x * gridDim.x;
    int u = blockIdx.x * blockDim.x + threadIdx.x;
#pragma unroll 2
    for (int k = 0; k < 2; k++) {
        int task = u + k * stride;
        if (task < T) {
            int e = task >> 1;
            int h = task & 1;
            int s = __ldg(&src[e]);
            int d = __ldg(&dst[e]);
            const uint4* yp = (const uint4*)(g_yh + (size_t)s * ROWH) + h;
            uint4 v = __ldg(yp);
            __half* ap = g_acch + (size_t)d * ROWH + h * 8;
            asm volatile("red.global.add.noftz.v4.f16x2 [%0], {%1,%2,%3,%4};"
                         :: "l"(ap), "r"(v.x), "r"(v.y), "r"(v.z), "r"(v.w)
                         : "memory");
        }
    }
}

// ---------------- K4: per-node epilogue (+ re-zero deg for next call) ----------------
__device__ __forceinline__ float tanh_fast(float x) {
    float y;
    asm("tanh.approx.f32 %0, %1;" : "=f"(y) : "f"(x));
    return y;
}

__global__ void k_final(const float* __restrict__ ow, const float* __restrict__ ob,
                        float* __restrict__ out, int n) {
    int i = blockIdx.x * blockDim.x + threadIdx.x;
    if (i >= n) return;

    g_deg[i] = 0;  // leave deg zeroed for the next kernel_launch call

    float azh[4], bzh[4], ah[4], bh[4], wh[NPER];
#pragma unroll
    for (int c = 0; c < 4; c++) {
        azh[c] = __ldg(&g_cf[c]);
        bzh[c] = __ldg(&g_cf[4 + c]);
        ah[c]  = __ldg(&g_cf[8 + c]);
        bh[c]  = __ldg(&g_cf[12 + c]);
    }
#pragma unroll
    for (int p = 0; p < NPER; p++) wh[p] = __ldg(&g_cf[16 + p]);

    float dinv = g_dinv[i];

    const uint4* ar = (const uint4*)(g_acch + (size_t)i * ROWH);
    uint4 alo = ar[0];
    uint2 ahi = *(const uint2*)(ar + 1);
    float av[NPER];
    {
        float2 t;
        t = __half22float2(*(__half2*)&alo.x); av[0] = t.x; av[1] = t.y;
        t = __half22float2(*(__half2*)&alo.y); av[2] = t.x; av[3] = t.y;
        t = __half22float2(*(__half2*)&alo.z); av[4] = t.x; av[5] = t.y;
        t = __half22float2(*(__half2*)&alo.w); av[6] = t.x; av[7] = t.y;
        t = __half22float2(*(__half2*)&ahi.x); av[8] = t.x; av[9] = t.y;
        t = __half22float2(*(__half2*)&ahi.y); av[10] = t.x; av[11] = t.y;
    }

    float H[4] = {0.f, 0.f, 0.f, 0.f};
#pragma unroll
    for (int p = 0; p < NPER; p++) {
        float sp = dinv * av[p];   // acc already includes self-loop message
        float w = wh[p];           // = softmax_p / 2
#pragma unroll
        for (int c = 0; c < 4; c++) {
            float t1 = tanh_fast(fmaf(sp, azh[c], bzh[c]));
            float t2 = tanh_fast(fmaf(sp, ah[c], bh[c]));
            H[c] = fmaf(w * (1.0f - t1), t2, H[c]);
        }
    }

    float o[NPER];
#pragma unroll
    for (int f = 0; f < NPER; f++) {
        float v = __ldg(&ob[f]);
#pragma unroll
        for (int c = 0; c < 4; c++) v = fmaf(H[c], __ldg(&ow[c * NPER + f]), v);
        o[f] = v;
    }
    float4* orow = (float4*)(out + (size_t)i * NPER);
    orow[0] = make_float4(o[0], o[1], o[2], o[3]);
    orow[1] = make_float4(o[4], o[5], o[6], o[7]);
    orow[2] = make_float4(o[8], o[9], o[10], o[11]);
}

// ---------------- launch ----------------
extern "C" void kernel_launch(void* const* d_in, const int* in_sizes, int n_in,
                              void* d_out, int out_size) {
    const float* x  = (const float*)d_in[0];
    const int*   ei = (const int*)d_in[1];
    const float* cz_w = (const float*)d_in[2];
    const float* cz_b = (const float*)d_in[3];
    const float* lz_w = (const float*)d_in[4];
    const float* lz_b = (const float*)d_in[5];
    // d_in[6..9] = conv_r / lin_r : dead (multiplied by H0 == 0)
    const float* ch_w = (const float*)d_in[10];
    const float* ch_b = (const float*)d_in[11];
    const float* lh_w = (const float*)d_in[12];
    const float* lh_b = (const float*)d_in[13];
    const float* att  = (const float*)d_in[14];
    const float* ow   = (const float*)d_in[15];
    const float* ob   = (const float*)d_in[16];
    float* out = (float*)d_out;

    int N = in_sizes[0] / NPER;
    int E = in_sizes[1] / 2;
    const int* src = ei;
    const int* dst = ei + E;

    const int TB = 256;
    int q8 = (E >> 3) + 1;
    int degThreads = q8 > N ? q8 : N;
    k_deg<<<(degThreads + TB - 1) / TB, TB>>>(dst, E, x, N,
                                              cz_w, cz_b, lz_w, lz_b,
                                              ch_w, ch_b, lh_w, lh_b, att);
    k_prep<<<(N + TB - 1) / TB, TB>>>(N);
    // 2E tasks, 2 tasks per thread (strided so lane pairs share a row sector)
    int T = 2 * E;
    int nthreads = (T + 1) / 2;
    k_scatter<<<(nthreads + TB - 1) / TB, TB>>>(src, dst, E);
    k_final<<<(N + TB - 1) / TB, TB>>>(ow, ob, out, N);
}

// round 13
// speedup vs baseline: 1.0048x; 1.0048x over previous
#include <cuda_runtime.h>
#include <cuda_fp16.h>
#include <cstdint>

#define NODES_MAX 100000
#define NPER 12
#define ROWH 16   // padded fp16 row: 16 halves = 32 B = one L2 sector

__device__ int    g_deg[NODES_MAX];          // zero-init at load; k_final re-zeroes each call
__device__ float  g_dinv[NODES_MAX];
__device__ __align__(32) __half g_yraw[NODES_MAX * ROWH];  // x as fp16, unscaled (written by k_deg)
__device__ __align__(32) __half g_yh[NODES_MAX * ROWH];    // y = x * dinv_src, fp16 (last 4 halves zero)
__device__ __align__(32) __half g_acch[NODES_MAX * ROWH];  // fp16 accumulator (seeded with y = self loop)
// folded coefficients: azh[4] (=az/2), bzh[4] (=bz/2), ah[4], bh[4], wh[12] (=softmax/2)
__device__ float g_cf[32];

// ---------------- K1: degree count (8 edges/thread) + x->fp16 convert + coef fold ----------------
__global__ void k_deg(const int* __restrict__ dst, int E,
                      const float* __restrict__ x, int n_nodes,
                      const float* __restrict__ cz_w, const float* __restrict__ cz_b,
                      const float* __restrict__ lz_w, const float* __restrict__ lz_b,
                      const float* __restrict__ ch_w, const float* __restrict__ ch_b,
                      const float* __restrict__ lh_w, const float* __restrict__ lh_b,
                      const float* __restrict__ att) {
    int i = blockIdx.x * blockDim.x + threadIdx.x;
    int e8 = E >> 3;
    if (i < e8) {
        int4 a = ((const int4*)dst)[2 * i];
        int4 b = ((const int4*)dst)[2 * i + 1];
        atomicAdd(&g_deg[a.x], 1);
        atomicAdd(&g_deg[a.y], 1);
        atomicAdd(&g_deg[a.z], 1);
        atomicAdd(&g_deg[a.w], 1);
        atomicAdd(&g_deg[b.x], 1);
        atomicAdd(&g_deg[b.y], 1);
        atomicAdd(&g_deg[b.z], 1);
        atomicAdd(&g_deg[b.w], 1);
    } else if (i == e8) {
        for (int r = e8 * 8; r < E; r++) atomicAdd(&g_deg[dst[r]], 1);
    }
    // overlap: convert x rows to raw fp16 using idle DRAM bandwidth
    if (i < n_nodes) {
        const float4* xr = (const float4*)(x + (size_t)i * NPER);
        float4 a = xr[0], b = xr[1], c = xr[2];
        __half2 h0 = __floats2half2_rn(a.x, a.y);
        __half2 h1 = __floats2half2_rn(a.z, a.w);
        __half2 h2 = __floats2half2_rn(b.x, b.y);
        __half2 h3 = __floats2half2_rn(b.z, b.w);
        __half2 h4 = __floats2half2_rn(c.x, c.y);
        __half2 h5 = __floats2half2_rn(c.z, c.w);
        uint4 lo, hi;
        lo.x = *(unsigned*)&h0; lo.y = *(unsigned*)&h1;
        lo.z = *(unsigned*)&h2; lo.w = *(unsigned*)&h3;
        hi.x = *(unsigned*)&h4; hi.y = *(unsigned*)&h5;
        hi.z = 0; hi.w = 0;
        uint4* row = (uint4*)(g_yraw + (size_t)i * ROWH);
        row[0] = lo;
        row[1] = hi;
    }
    if (blockIdx.x == 0 && threadIdx.x == 0) {
        for (int c = 0; c < 4; c++) {
            float a = 0.f, b = lz_b[c];
            float a2 = 0.f, b2 = lh_b[c];
            for (int k = 0; k < 4; k++) {
                float lz = lz_w[k * 4 + c];
                float lh = lh_w[k * 4 + c];
                a  += cz_w[k] * lz;
                b  += cz_b[k] * lz;
                a2 += ch_w[k] * lh;
                b2 += ch_b[k] * lh;
            }
            g_cf[c]     = 0.5f * a;   // halved: sigmoid(x) = 0.5 + 0.5*tanh(x/2)
            g_cf[4 + c] = 0.5f * b;
            g_cf[8 + c]  = a2;
            g_cf[12 + c] = b2;
        }
        float m = -1e30f;
        for (int p = 0; p < NPER; p++) m = fmaxf(m, att[p]);
        float sum = 0.f;
        float e[NPER];
        for (int p = 0; p < NPER; p++) { e[p] = __expf(att[p] - m); sum += e[p]; }
        float inv = 0.5f / sum;  // absorbs the 0.5 from (1-z) = 0.5*(1-t1)
        for (int p = 0; p < NPER; p++) g_cf[16 + p] = e[p] * inv;
    }
}

// ---------------- K2: dinv + scale raw fp16 rows; acc seeded with y (self loop) ----------------
__device__ __forceinline__ unsigned scaleh2(unsigned a, float s) {
    float2 f = __half22float2(*(__half2*)&a);
    __half2 r = __floats2half2_rn(f.x * s, f.y * s);
    return *(unsigned*)&r;
}

__global__ void k_prep(int n) {
    int i = blockIdx.x * blockDim.x + threadIdx.x;
    if (i >= n) return;
    float dinv = rsqrtf((float)(g_deg[i] + 1));  // +1 for self loop
    g_dinv[i] = dinv;
    const uint4* rr = (const uint4*)(g_yraw + (size_t)i * ROWH);
    uint4 r0 = rr[0];
    uint4 r1 = rr[1];
    uint4 lo, hi;
    lo.x = scaleh2(r0.x, dinv);
    lo.y = scaleh2(r0.y, dinv);
    lo.z = scaleh2(r0.z, dinv);
    lo.w = scaleh2(r0.w, dinv);
    hi.x = scaleh2(r1.x, dinv);
    hi.y = scaleh2(r1.y, dinv);
    hi.z = 0;
    hi.w = 0;
    uint4* row = (uint4*)(g_yh + (size_t)i * ROWH);
    row[0] = lo;
    row[1] = hi;
    // seed accumulator with the self-loop message:
    // final s = dinv * (y_self + sum_edges y_src) = dinv^2*x + dinv*sum
    uint4* arow = (uint4*)(g_acch + (size_t)i * ROWH);
    arow[0] = lo;
    arow[1] = hi;
}

// ---------------- K3: edge scatter, 2 lanes per edge (half-row tasks), 1 task/thread ----------------
__global__ void k_scatter(const int* __restrict__ src, const int* __restrict__ dst, int E) {
    int task = blockIdx.x * blockDim.x + threadIdx.x;
    if (task >= 2 * E) return;
    int e = task >> 1;
    int h = task & 1;
    int s = __ldg(&src[e]);
    int d = __ldg(&dst[e]);
    const uint4* yp = (const uint4*)(g_yh + (size_t)s * ROWH) + h;
    uint4 v = __ldg(yp);
    __half* ap = g_acch + (size_t)d * ROWH + h * 8;
    asm volatile("red.global.add.noftz.v4.f16x2 [%0], {%1,%2,%3,%4};"
                 :: "l"(ap), "r"(v.x), "r"(v.y), "r"(v.z), "r"(v.w)
                 : "memory");
}

// ---------------- K4: per-node epilogue (+ re-zero deg for next call) ----------------
__device__ __forceinline__ float tanh_fast(float x) {
    float y;
    asm("tanh.approx.f32 %0, %1;" : "=f"(y) : "f"(x));
    return y;
}

__global__ void k_final(const float* __restrict__ ow, const float* __restrict__ ob,
                        float* __restrict__ out, int n) {
    int i = blockIdx.x * blockDim.x + threadIdx.x;
    if (i >= n) return;

    g_deg[i] = 0;  // leave deg zeroed for the next kernel_launch call

    float azh[4], bzh[4], ah[4], bh[4], wh[NPER];
#pragma unroll
    for (int c = 0; c < 4; c++) {
        azh[c] = __ldg(&g_cf[c]);
        bzh[c] = __ldg(&g_cf[4 + c]);
        ah[c]  = __ldg(&g_cf[8 + c]);
        bh[c]  = __ldg(&g_cf[12 + c]);
    }
#pragma unroll
    for (int p = 0; p < NPER; p++) wh[p] = __ldg(&g_cf[16 + p]);

    float dinv = g_dinv[i];

    const uint4* ar = (const uint4*)(g_acch + (size_t)i * ROWH);
    uint4 alo = ar[0];
    uint2 ahi = *(const uint2*)(ar + 1);
    float av[NPER];
    {
        float2 t;
        t = __half22float2(*(__half2*)&alo.x); av[0] = t.x; av[1] = t.y;
        t = __half22float2(*(__half2*)&alo.y); av[2] = t.x; av[3] = t.y;
        t = __half22float2(*(__half2*)&alo.z); av[4] = t.x; av[5] = t.y;
        t = __half22float2(*(__half2*)&alo.w); av[6] = t.x; av[7] = t.y;
        t = __half22float2(*(__half2*)&ahi.x); av[8] = t.x; av[9] = t.y;
        t = __half22float2(*(__half2*)&ahi.y); av[10] = t.x; av[11] = t.y;
    }

    float H[4] = {0.f, 0.f, 0.f, 0.f};
#pragma unroll
    for (int p = 0; p < NPER; p++) {
        float sp = dinv * av[p];   // acc already includes self-loop message
        float w = wh[p];           // = softmax_p / 2
#pragma unroll
        for (int c = 0; c < 4; c++) {
            float t1 = tanh_fast(fmaf(sp, azh[c], bzh[c]));
            float t2 = tanh_fast(fmaf(sp, ah[c], bh[c]));
            H[c] = fmaf(w * (1.0f - t1), t2, H[c]);
        }
    }

    float o[NPER];
#pragma unroll
    for (int f = 0; f < NPER; f++) {
        float v = __ldg(&ob[f]);
#pragma unroll
        for (int c = 0; c < 4; c++) v = fmaf(H[c], __ldg(&ow[c * NPER + f]), v);
        o[f] = v;
    }
    float4* orow = (float4*)(out + (size_t)i * NPER);
    orow[0] = make_float4(o[0], o[1], o[2], o[3]);
    orow[1] = make_float4(o[4], o[5], o[6], o[7]);
    orow[2] = make_float4(o[8], o[9], o[10], o[11]);
}

// ---------------- launch ----------------
extern "C" void kernel_launch(void* const* d_in, const int* in_sizes, int n_in,
                              void* d_out, int out_size) {
    const float* x  = (const float*)d_in[0];
    const int*   ei = (const int*)d_in[1];
    const float* cz_w = (const float*)d_in[2];
    const float* cz_b = (const float*)d_in[3];
    const float* lz_w = (const float*)d_in[4];
    const float* lz_b = (const float*)d_in[5];
    // d_in[6..9] = conv_r / lin_r : dead (multiplied by H0 == 0)
    const float* ch_w = (const float*)d_in[10];
    const float* ch_b = (const float*)d_in[11];
    const float* lh_w = (const float*)d_in[12];
    const float* lh_b = (const float*)d_in[13];
    const float* att  = (const float*)d_in[14];
    const float* ow   = (const float*)d_in[15];
    const float* ob   = (const float*)d_in[16];
    float* out = (float*)d_out;

    int N = in_sizes[0] / NPER;
    int E = in_sizes[1] / 2;
    const int* src = ei;
    const int* dst = ei + E;

    const int TB = 256;
    int q8 = (E >> 3) + 1;
    int degThreads = q8 > N ? q8 : N;
    k_deg<<<(degThreads + TB - 1) / TB, TB>>>(dst, E, x, N,
                                              cz_w, cz_b, lz_w, lz_b,
                                              ch_w, ch_b, lh_w, lh_b, att);
    k_prep<<<(N + TB - 1) / TB, TB>>>(N);
    int T = 2 * E;
    k_scatter<<<(T + TB - 1) / TB, TB>>>(src, dst, E);
    k_final<<<(N + 127) / 128, 128>>>(ow, ob, out, N);
}

// round 14
// speedup vs baseline: 1.0161x; 1.0112x over previous
#include <cuda_runtime.h>
#include <cuda_fp16.h>
#include <cstdint>

#define NODES_MAX 100000
#define NPER 12
#define ROWH 16   // padded fp16 row: 16 halves = 32 B = one L2 sector

#define PDL_TRIGGER() asm volatile("griddepcontrol.launch_dependents;" ::: "memory")
#define PDL_WAIT()    asm volatile("griddepcontrol.wait;" ::: "memory")

__device__ int    g_deg[NODES_MAX];          // zero-init at load; k_final re-zeroes each call
__device__ float  g_dinv[NODES_MAX];
__device__ __align__(32) __half g_yraw[NODES_MAX * ROWH];  // x as fp16, unscaled (written by k_deg)
__device__ __align__(32) __half g_yh[NODES_MAX * ROWH];    // y = x * dinv_src, fp16 (last 4 halves zero)
__device__ __align__(32) __half g_acch[NODES_MAX * ROWH];  // fp16 accumulator (seeded with y = self loop)
// folded coefficients: azh[4] (=az/2), bzh[4] (=bz/2), ah[4], bh[4], wh[12] (=softmax/2)
__device__ float g_cf[32];

// ---------------- K1: degree count (8 edges/thread) + x->fp16 convert + coef fold ----------------
__global__ void k_deg(const int* __restrict__ dst, int E,
                      const float* __restrict__ x, int n_nodes,
                      const float* __restrict__ cz_w, const float* __restrict__ cz_b,
                      const float* __restrict__ lz_w, const float* __restrict__ lz_b,
                      const float* __restrict__ ch_w, const float* __restrict__ ch_b,
                      const float* __restrict__ lh_w, const float* __restrict__ lh_b,
                      const float* __restrict__ att) {
    int i = blockIdx.x * blockDim.x + threadIdx.x;
    int e8 = E >> 3;
    if (i < e8) {
        int4 a = ((const int4*)dst)[2 * i];
        int4 b = ((const int4*)dst)[2 * i + 1];
        atomicAdd(&g_deg[a.x], 1);
        atomicAdd(&g_deg[a.y], 1);
        atomicAdd(&g_deg[a.z], 1);
        atomicAdd(&g_deg[a.w], 1);
        atomicAdd(&g_deg[b.x], 1);
        atomicAdd(&g_deg[b.y], 1);
        atomicAdd(&g_deg[b.z], 1);
        atomicAdd(&g_deg[b.w], 1);
    } else if (i == e8) {
        for (int r = e8 * 8; r < E; r++) atomicAdd(&g_deg[dst[r]], 1);
    }
    // overlap: convert x rows to raw fp16 using idle DRAM bandwidth
    if (i < n_nodes) {
        const float4* xr = (const float4*)(x + (size_t)i * NPER);
        float4 a = xr[0], b = xr[1], c = xr[2];
        __half2 h0 = __floats2half2_rn(a.x, a.y);
        __half2 h1 = __floats2half2_rn(a.z, a.w);
        __half2 h2 = __floats2half2_rn(b.x, b.y);
        __half2 h3 = __floats2half2_rn(b.z, b.w);
        __half2 h4 = __floats2half2_rn(c.x, c.y);
        __half2 h5 = __floats2half2_rn(c.z, c.w);
        uint4 lo, hi;
        lo.x = *(unsigned*)&h0; lo.y = *(unsigned*)&h1;
        lo.z = *(unsigned*)&h2; lo.w = *(unsigned*)&h3;
        hi.x = *(unsigned*)&h4; hi.y = *(unsigned*)&h5;
        hi.z = 0; hi.w = 0;
        uint4* row = (uint4*)(g_yraw + (size_t)i * ROWH);
        row[0] = lo;
        row[1] = hi;
    }
    if (blockIdx.x == 0 && threadIdx.x == 0) {
        for (int c = 0; c < 4; c++) {
            float a = 0.f, b = lz_b[c];
            float a2 = 0.f, b2 = lh_b[c];
            for (int k = 0; k < 4; k++) {
                float lz = lz_w[k * 4 + c];
                float lh = lh_w[k * 4 + c];
                a  += cz_w[k] * lz;
                b  += cz_b[k] * lz;
                a2 += ch_w[k] * lh;
                b2 += ch_b[k] * lh;
            }
            g_cf[c]     = 0.5f * a;   // halved: sigmoid(x) = 0.5 + 0.5*tanh(x/2)
            g_cf[4 + c] = 0.5f * b;
            g_cf[8 + c]  = a2;
            g_cf[12 + c] = b2;
        }
        float m = -1e30f;
        for (int p = 0; p < NPER; p++) m = fmaxf(m, att[p]);
        float sum = 0.f;
        float e[NPER];
        for (int p = 0; p < NPER; p++) { e[p] = __expf(att[p] - m); sum += e[p]; }
        float inv = 0.5f / sum;  // absorbs the 0.5 from (1-z) = 0.5*(1-t1)
        for (int p = 0; p < NPER; p++) g_cf[16 + p] = e[p] * inv;
    }
    PDL_TRIGGER();  // all our writes are done; dependents may launch
}

// ---------------- K2: dinv + scale raw fp16 rows; acc seeded with y (self loop) ----------------
__device__ __forceinline__ unsigned scaleh2(unsigned a, float s) {
    float2 f = __half22float2(*(__half2*)&a);
    __half2 r = __floats2half2_rn(f.x * s, f.y * s);
    return *(unsigned*)&r;
}

__global__ void k_prep(int n) {
    int i = blockIdx.x * blockDim.x + threadIdx.x;
    if (i >= n) { PDL_TRIGGER(); return; }
    PDL_WAIT();   // g_deg / g_yraw produced by k_deg
    float dinv = rsqrtf((float)(g_deg[i] + 1));  // +1 for self loop
    g_dinv[i] = dinv;
    const uint4* rr = (const uint4*)(g_yraw + (size_t)i * ROWH);
    uint4 r0 = rr[0];
    uint4 r1 = rr[1];
    uint4 lo, hi;
    lo.x = scaleh2(r0.x, dinv);
    lo.y = scaleh2(r0.y, dinv);
    lo.z = scaleh2(r0.z, dinv);
    lo.w = scaleh2(r0.w, dinv);
    hi.x = scaleh2(r1.x, dinv);
    hi.y = scaleh2(r1.y, dinv);
    hi.z = 0;
    hi.w = 0;
    uint4* row = (uint4*)(g_yh + (size_t)i * ROWH);
    row[0] = lo;
    row[1] = hi;
    // seed accumulator with the self-loop message:
    // final s = dinv * (y_self + sum_edges y_src) = dinv^2*x + dinv*sum
    uint4* arow = (uint4*)(g_acch + (size_t)i * ROWH);
    arow[0] = lo;
    arow[1] = hi;
    PDL_TRIGGER();
}

// ---------------- K3: edge scatter, 2 lanes per edge (half-row tasks), 1 task/thread ----------------
__global__ void k_scatter(const int* __restrict__ src, const int* __restrict__ dst, int E) {
    int task = blockIdx.x * blockDim.x + threadIdx.x;
    if (task >= 2 * E) { PDL_TRIGGER(); return; }
    int e = task >> 1;
    int h = task & 1;
    // src/dst are harness inputs (written before the graph) — safe to load pre-wait
    int s = __ldg(&src[e]);
    int d = __ldg(&dst[e]);
    PDL_WAIT();   // g_yh / g_acch produced by k_prep
    const uint4* yp = (const uint4*)(g_yh + (size_t)s * ROWH) + h;
    uint4 v = __ldg(yp);
    __half* ap = g_acch + (size_t)d * ROWH + h * 8;
    asm volatile("red.global.add.noftz.v4.f16x2 [%0], {%1,%2,%3,%4};"
                 :: "l"(ap), "r"(v.x), "r"(v.y), "r"(v.z), "r"(v.w)
                 : "memory");
    PDL_TRIGGER();
}

// ---------------- K4: per-node epilogue (+ re-zero deg for next call) ----------------
__device__ __forceinline__ float tanh_fast(float x) {
    float y;
    asm("tanh.approx.f32 %0, %1;" : "=f"(y) : "f"(x));
    return y;
}

__global__ void k_final(const float* __restrict__ ow, const float* __restrict__ ob,
                        float* __restrict__ out, int n) {
    int i = blockIdx.x * blockDim.x + threadIdx.x;
    if (i >= n) return;

    // prologue: load weights (harness inputs, pre-graph) before waiting
    float o_b[NPER], o_w[4][NPER];
#pragma unroll
    for (int f = 0; f < NPER; f++) o_b[f] = __ldg(&ob[f]);
#pragma unroll
    for (int c = 0; c < 4; c++)
#pragma unroll
        for (int f = 0; f < NPER; f++) o_w[c][f] = __ldg(&ow[c * NPER + f]);

    PDL_WAIT();   // g_acch complete (scatter), g_cf/g_dinv transitively complete

    g_deg[i] = 0;  // leave deg zeroed for the next kernel_launch call

    float azh[4], bzh[4], ah[4], bh[4], wh[NPER];
#pragma unroll
    for (int c = 0; c < 4; c++) {
        azh[c] = __ldg(&g_cf[c]);
        bzh[c] = __ldg(&g_cf[4 + c]);
        ah[c]  = __ldg(&g_cf[8 + c]);
        bh[c]  = __ldg(&g_cf[12 + c]);
    }
#pragma unroll
    for (int p = 0; p < NPER; p++) wh[p] = __ldg(&g_cf[16 + p]);

    float dinv = g_dinv[i];

    const uint4* ar = (const uint4*)(g_acch + (size_t)i * ROWH);
    uint4 alo = ar[0];
    uint2 ahi = *(const uint2*)(ar + 1);
    float av[NPER];
    {
        float2 t;
        t = __half22float2(*(__half2*)&alo.x); av[0] = t.x; av[1] = t.y;
        t = __half22float2(*(__half2*)&alo.y); av[2] = t.x; av[3] = t.y;
        t = __half22float2(*(__half2*)&alo.z); av[4] = t.x; av[5] = t.y;
        t = __half22float2(*(__half2*)&alo.w); av[6] = t.x; av[7] = t.y;
        t = __half22float2(*(__half2*)&ahi.x); av[8] = t.x; av[9] = t.y;
        t = __half22float2(*(__half2*)&ahi.y); av[10] = t.x; av[11] = t.y;
    }

    float H[4] = {0.f, 0.f, 0.f, 0.f};
#pragma unroll
    for (int p = 0; p < NPER; p++) {
        float sp = dinv * av[p];   // acc already includes self-loop message
        float w = wh[p];           // = softmax_p / 2
#pragma unroll
        for (int c = 0; c < 4; c++) {
            float t1 = tanh_fast(fmaf(sp, azh[c], bzh[c]));
            float t2 = tanh_fast(fmaf(sp, ah[c], bh[c]));
            H[c] = fmaf(w * (1.0f - t1), t2, H[c]);
        }
    }

    float o[NPER];
#pragma unroll
    for (int f = 0; f < NPER; f++) {
        float v = o_b[f];
#pragma unroll
        for (int c = 0; c < 4; c++) v = fmaf(H[c], o_w[c][f], v);
        o[f] = v;
    }
    float4* orow = (float4*)(out + (size_t)i * NPER);
    orow[0] = make_float4(o[0], o[1], o[2], o[3]);
    orow[1] = make_float4(o[4], o[5], o[6], o[7]);
    orow[2] = make_float4(o[8], o[9], o[10], o[11]);
}

// ---------------- launch ----------------
static void launch_pdl(void* fn, dim3 grid, dim3 block, void** args) {
    cudaLaunchConfig_t cfg = {};
    cfg.gridDim = grid;
    cfg.blockDim = block;
    cfg.dynamicSmemBytes = 0;
    cfg.stream = 0;
    cudaLaunchAttribute attr[1];
    attr[0].id = cudaLaunchAttributeProgrammaticStreamSerialization;
    attr[0].val.programmaticStreamSerializationAllowed = 1;
    cfg.attrs = attr;
    cfg.numAttrs = 1;
    cudaLaunchKernelExC(&cfg, fn, args);
}

extern "C" void kernel_launch(void* const* d_in, const int* in_sizes, int n_in,
                              void* d_out, int out_size) {
    const float* x  = (const float*)d_in[0];
    const int*   ei = (const int*)d_in[1];
    const float* cz_w = (const float*)d_in[2];
    const float* cz_b = (const float*)d_in[3];
    const float* lz_w = (const float*)d_in[4];
    const float* lz_b = (const float*)d_in[5];
    // d_in[6..9] = conv_r / lin_r : dead (multiplied by H0 == 0)
    const float* ch_w = (const float*)d_in[10];
    const float* ch_b = (const float*)d_in[11];
    const float* lh_w = (const float*)d_in[12];
    const float* lh_b = (const float*)d_in[13];
    const float* att  = (const float*)d_in[14];
    const float* ow   = (const float*)d_in[15];
    const float* ob   = (const float*)d_in[16];
    float* out = (float*)d_out;

    int N = in_sizes[0] / NPER;
    int E = in_sizes[1] / 2;
    const int* src = ei;
    const int* dst = ei + E;

    const int TB = 256;
    int q8 = (E >> 3) + 1;
    int degThreads = q8 > N ? q8 : N;
    k_deg<<<(degThreads + TB - 1) / TB, TB>>>(dst, E, x, N,
                                              cz_w, cz_b, lz_w, lz_b,
                                              ch_w, ch_b, lh_w, lh_b, att);
    {
        void* args[] = { (void*)&N };
        launch_pdl((void*)k_prep, dim3((N + TB - 1) / TB), dim3(TB), args);
    }
    {
        int T = 2 * E;
        void* args[] = { (void*)&src, (void*)&dst, (void*)&E };
        launch_pdl((void*)k_scatter, dim3((T + TB - 1) / TB), dim3(TB), args);
    }
    {
        void* args[] = { (void*)&ow, (void*)&ob, (void*)&out, (void*)&N };
        launch_pdl((void*)k_final, dim3((N + 127) / 128), dim3(128), args);
    }
}

// round 15
// speedup vs baseline: 1.0166x; 1.0005x over previous
#include <cuda_runtime.h>
#include <cuda_fp16.h>
#include <cstdint>

#define NODES_MAX 100000
#define NPER 12
#define ROWH 16   // padded fp16 row: 16 halves = 32 B = one L2 sector

#define PDL_TRIGGER() asm volatile("griddepcontrol.launch_dependents;" ::: "memory")
#define PDL_WAIT()    asm volatile("griddepcontrol.wait;" ::: "memory")

__device__ int    g_deg[NODES_MAX];          // zero-init at load; k_final re-zeroes each call
__device__ float  g_dinv[NODES_MAX];
__device__ __align__(32) __half g_yraw[NODES_MAX * ROWH];  // x as fp16, unscaled (written by k_deg)
__device__ __align__(32) __half g_yh[NODES_MAX * ROWH];    // y = x * dinv_src, fp16 (last 4 halves zero)
__device__ __align__(32) __half g_acch[NODES_MAX * ROWH];  // fp16 accumulator (seeded with y = self loop)
// folded coefficients: azh[4] (=az/2), bzh[4] (=bz/2), ah[4], bh[4], wh[12] (=softmax/2)
__device__ float g_cf[32];

// ---------------- K1: degree count (8 edges/thread) + x->fp16 convert + coef fold ----------------
__global__ void k_deg(const int* __restrict__ dst, int E,
                      const float* __restrict__ x, int n_nodes,
                      const float* __restrict__ cz_w, const float* __restrict__ cz_b,
                      const float* __restrict__ lz_w, const float* __restrict__ lz_b,
                      const float* __restrict__ ch_w, const float* __restrict__ ch_b,
                      const float* __restrict__ lh_w, const float* __restrict__ lh_b,
                      const float* __restrict__ att) {
    int i = blockIdx.x * blockDim.x + threadIdx.x;
    int e8 = E >> 3;
    if (i < e8) {
        int4 a = ((const int4*)dst)[2 * i];
        int4 b = ((const int4*)dst)[2 * i + 1];
        atomicAdd(&g_deg[a.x], 1);
        atomicAdd(&g_deg[a.y], 1);
        atomicAdd(&g_deg[a.z], 1);
        atomicAdd(&g_deg[a.w], 1);
        atomicAdd(&g_deg[b.x], 1);
        atomicAdd(&g_deg[b.y], 1);
        atomicAdd(&g_deg[b.z], 1);
        atomicAdd(&g_deg[b.w], 1);
    } else if (i == e8) {
        for (int r = e8 * 8; r < E; r++) atomicAdd(&g_deg[dst[r]], 1);
    }
    // overlap: convert x rows to raw fp16 using idle DRAM bandwidth
    if (i < n_nodes) {
        const float4* xr = (const float4*)(x + (size_t)i * NPER);
        float4 a = xr[0], b = xr[1], c = xr[2];
        __half2 h0 = __floats2half2_rn(a.x, a.y);
        __half2 h1 = __floats2half2_rn(a.z, a.w);
        __half2 h2 = __floats2half2_rn(b.x, b.y);
        __half2 h3 = __floats2half2_rn(b.z, b.w);
        __half2 h4 = __floats2half2_rn(c.x, c.y);
        __half2 h5 = __floats2half2_rn(c.z, c.w);
        uint4 lo, hi;
        lo.x = *(unsigned*)&h0; lo.y = *(unsigned*)&h1;
        lo.z = *(unsigned*)&h2; lo.w = *(unsigned*)&h3;
        hi.x = *(unsigned*)&h4; hi.y = *(unsigned*)&h5;
        hi.z = 0; hi.w = 0;
        uint4* row = (uint4*)(g_yraw + (size_t)i * ROWH);
        row[0] = lo;
        row[1] = hi;
    }
    if (blockIdx.x == 0 && threadIdx.x == 0) {
        for (int c = 0; c < 4; c++) {
            float a = 0.f, b = lz_b[c];
            float a2 = 0.f, b2 = lh_b[c];
            for (int k = 0; k < 4; k++) {
                float lz = lz_w[k * 4 + c];
                float lh = lh_w[k * 4 + c];
                a  += cz_w[k] * lz;
                b  += cz_b[k] * lz;
                a2 += ch_w[k] * lh;
                b2 += ch_b[k] * lh;
            }
            g_cf[c]     = 0.5f * a;   // halved: sigmoid(x) = 0.5 + 0.5*tanh(x/2)
            g_cf[4 + c] = 0.5f * b;
            g_cf[8 + c]  = a2;
            g_cf[12 + c] = b2;
        }
        float m = -1e30f;
        for (int p = 0; p < NPER; p++) m = fmaxf(m, att[p]);
        float sum = 0.f;
        float e[NPER];
        for (int p = 0; p < NPER; p++) { e[p] = __expf(att[p] - m); sum += e[p]; }
        float inv = 0.5f / sum;  // absorbs the 0.5 from (1-z) = 0.5*(1-t1)
        for (int p = 0; p < NPER; p++) g_cf[16 + p] = e[p] * inv;
    }
    PDL_TRIGGER();  // all our writes are done; dependents may launch
}

// ---------------- K2: dinv + scale raw fp16 rows; acc seeded with y (self loop) ----------------
__device__ __forceinline__ unsigned scaleh2(unsigned a, float s) {
    float2 f = __half22float2(*(__half2*)&a);
    __half2 r = __floats2half2_rn(f.x * s, f.y * s);
    return *(unsigned*)&r;
}

__global__ void k_prep(int n) {
    int i = blockIdx.x * blockDim.x + threadIdx.x;
    if (i >= n) { PDL_TRIGGER(); return; }
    PDL_WAIT();   // g_deg / g_yraw produced by k_deg
    float dinv = rsqrtf((float)(g_deg[i] + 1));  // +1 for self loop
    g_dinv[i] = dinv;
    const uint4* rr = (const uint4*)(g_yraw + (size_t)i * ROWH);
    uint4 r0 = rr[0];
    uint4 r1 = rr[1];
    uint4 lo, hi;
    lo.x = scaleh2(r0.x, dinv);
    lo.y = scaleh2(r0.y, dinv);
    lo.z = scaleh2(r0.z, dinv);
    lo.w = scaleh2(r0.w, dinv);
    hi.x = scaleh2(r1.x, dinv);
    hi.y = scaleh2(r1.y, dinv);
    hi.z = 0;
    hi.w = 0;
    uint4* row = (uint4*)(g_yh + (size_t)i * ROWH);
    row[0] = lo;
    row[1] = hi;
    // seed accumulator with the self-loop message:
    // final s = dinv * (y_self + sum_edges y_src) = dinv^2*x + dinv*sum
    uint4* arow = (uint4*)(g_acch + (size_t)i * ROWH);
    arow[0] = lo;
    arow[1] = hi;
    PDL_TRIGGER();
}

// ---------------- K3: edge scatter, 2 lanes per edge; shfl-shared indices ----------------
__global__ void k_scatter(const int* __restrict__ src, const int* __restrict__ dst, int E) {
    int task = blockIdx.x * blockDim.x + threadIdx.x;
    int e = task >> 1;
    int h = task & 1;
    bool live = (task < 2 * E);
    // even lane loads src[e], odd lane loads dst[e]; exchange via shfl.
    // Pair lanes share e, so partner lane (lane^1) holds the other index.
    int mine = 0;
    if (live) mine = h ? __ldg(&dst[e]) : __ldg(&src[e]);
    int other = __shfl_xor_sync(0xFFFFFFFFu, mine, 1);
    // even lane: mine=src, other=dst. odd lane: mine=dst, other=src.
    int s = h ? other : mine;
    int d = h ? mine : other;
    PDL_WAIT();   // g_yh / g_acch produced by k_prep
    if (live) {
        const uint4* yp = (const uint4*)(g_yh + (size_t)s * ROWH) + h;
        uint4 v = __ldg(yp);
        __half* ap = g_acch + (size_t)d * ROWH + h * 8;
        asm volatile("red.global.add.noftz.v4.f16x2 [%0], {%1,%2,%3,%4};"
                     :: "l"(ap), "r"(v.x), "r"(v.y), "r"(v.z), "r"(v.w)
                     : "memory");
    }
    PDL_TRIGGER();
}

// ---------------- K4: per-node epilogue (+ re-zero deg for next call) ----------------
__device__ __forceinline__ float tanh_fast(float x) {
    float y;
    asm("tanh.approx.f32 %0, %1;" : "=f"(y) : "f"(x));
    return y;
}

__global__ void k_final(const float* __restrict__ ow, const float* __restrict__ ob,
                        float* __restrict__ out, int n) {
    int i = blockIdx.x * blockDim.x + threadIdx.x;
    if (i >= n) return;

    // prologue: load weights (harness inputs, pre-graph) before waiting
    float o_b[NPER], o_w[4][NPER];
#pragma unroll
    for (int f = 0; f < NPER; f++) o_b[f] = __ldg(&ob[f]);
#pragma unroll
    for (int c = 0; c < 4; c++)
#pragma unroll
        for (int f = 0; f < NPER; f++) o_w[c][f] = __ldg(&ow[c * NPER + f]);

    PDL_WAIT();   // g_acch complete (scatter), g_cf/g_dinv transitively complete

    g_deg[i] = 0;  // leave deg zeroed for the next kernel_launch call

    float azh[4], bzh[4], ah[4], bh[4], wh[NPER];
#pragma unroll
    for (int c = 0; c < 4; c++) {
        azh[c] = __ldg(&g_cf[c]);
        bzh[c] = __ldg(&g_cf[4 + c]);
        ah[c]  = __ldg(&g_cf[8 + c]);
        bh[c]  = __ldg(&g_cf[12 + c]);
    }
#pragma unroll
    for (int p = 0; p < NPER; p++) wh[p] = __ldg(&g_cf[16 + p]);

    float dinv = g_dinv[i];

    const uint4* ar = (const uint4*)(g_acch + (size_t)i * ROWH);
    uint4 alo = ar[0];
    uint2 ahi = *(const uint2*)(ar + 1);
    float av[NPER];
    {
        float2 t;
        t = __half22float2(*(__half2*)&alo.x); av[0] = t.x; av[1] = t.y;
        t = __half22float2(*(__half2*)&alo.y); av[2] = t.x; av[3] = t.y;
        t = __half22float2(*(__half2*)&alo.z); av[4] = t.x; av[5] = t.y;
        t = __half22float2(*(__half2*)&alo.w); av[6] = t.x; av[7] = t.y;
        t = __half22float2(*(__half2*)&ahi.x); av[8] = t.x; av[9] = t.y;
        t = __half22float2(*(__half2*)&ahi.y); av[10] = t.x; av[11] = t.y;
    }

    float H[4] = {0.f, 0.f, 0.f, 0.f};
#pragma unroll
    for (int p = 0; p < NPER; p++) {
        float sp = dinv * av[p];   // acc already includes self-loop message
        float w = wh[p];           // = softmax_p / 2
#pragma unroll
        for (int c = 0; c < 4; c++) {
            float t1 = tanh_fast(fmaf(sp, azh[c], bzh[c]));
            float t2 = tanh_fast(fmaf(sp, ah[c], bh[c]));
            H[c] = fmaf(w * (1.0f - t1), t2, H[c]);
        }
    }

    float o[NPER];
#pragma unroll
    for (int f = 0; f < NPER; f++) {
        float v = o_b[f];
#pragma unroll
        for (int c = 0; c < 4; c++) v = fmaf(H[c], o_w[c][f], v);
        o[f] = v;
    }
    float4* orow = (float4*)(out + (size_t)i * NPER);
    orow[0] = make_float4(o[0], o[1], o[2], o[3]);
    orow[1] = make_float4(o[4], o[5], o[6], o[7]);
    orow[2] = make_float4(o[8], o[9], o[10], o[11]);
}

// ---------------- launch ----------------
static void launch_pdl(void* fn, dim3 grid, dim3 block, void** args) {
    cudaLaunchConfig_t cfg = {};
    cfg.gridDim = grid;
    cfg.blockDim = block;
    cfg.dynamicSmemBytes = 0;
    cfg.stream = 0;
    cudaLaunchAttribute attr[1];
    attr[0].id = cudaLaunchAttributeProgrammaticStreamSerialization;
    attr[0].val.programmaticStreamSerializationAllowed = 1;
    cfg.attrs = attr;
    cfg.numAttrs = 1;
    cudaLaunchKernelExC(&cfg, fn, args);
}

extern "C" void kernel_launch(void* const* d_in, const int* in_sizes, int n_in,
                              void* d_out, int out_size) {
    const float* x  = (const float*)d_in[0];
    const int*   ei = (const int*)d_in[1];
    const float* cz_w = (const float*)d_in[2];
    const float* cz_b = (const float*)d_in[3];
    const float* lz_w = (const float*)d_in[4];
    const float* lz_b = (const float*)d_in[5];
    // d_in[6..9] = conv_r / lin_r : dead (multiplied by H0 == 0)
    const float* ch_w = (const float*)d_in[10];
    const float* ch_b = (const float*)d_in[11];
    const float* lh_w = (const float*)d_in[12];
    const float* lh_b = (const float*)d_in[13];
    const float* att  = (const float*)d_in[14];
    const float* ow   = (const float*)d_in[15];
    const float* ob   = (const float*)d_in[16];
    float* out = (float*)d_out;

    int N = in_sizes[0] / NPER;
    int E = in_sizes[1] / 2;
    const int* src = ei;
    const int* dst = ei + E;

    const int TB = 256;
    int q8 = (E >> 3) + 1;
    int degThreads = q8 > N ? q8 : N;
    k_deg<<<(degThreads + TB - 1) / TB, TB>>>(dst, E, x, N,
                                              cz_w, cz_b, lz_w, lz_b,
                                              ch_w, ch_b, lh_w, lh_b, att);
    {
        void* args[] = { (void*)&N };
        launch_pdl((void*)k_prep, dim3((N + TB - 1) / TB), dim3(TB), args);
    }
    {
        int T = 2 * E;
        void* args[] = { (void*)&src, (void*)&dst, (void*)&E };
        launch_pdl((void*)k_scatter, dim3((T + 511) / 512), dim3(512), args);
    }
    {
        void* args[] = { (void*)&ow, (void*)&ob, (void*)&out, (void*)&N };
        launch_pdl((void*)k_final, dim3((N + 127) / 128), dim3(128), args);
    }
}